// round 13
// baseline (speedup 1.0000x reference)
#include <cuda_runtime.h>
#include <math.h>
#include <stdint.h>

constexpr long MTOK  = 16 * 512;     // 8192 tokens

// ---------------------------------------------------------------------------
// Scratch arena
// ---------------------------------------------------------------------------
constexpr long OFF_X    = 0;
constexpr long OFF_LN   = OFF_X    + MTOK * 256;
constexpr long OFF_XZ   = OFF_LN   + MTOK * 256;
constexpr long OFF_XC   = OFF_XZ   + 2 * MTOK * 512;
constexpr long OFF_DBC  = OFF_XC   + 2 * MTOK * 256;
constexpr long OFF_DT   = OFF_DBC  + 2 * MTOK * 40;
constexpr long OFF_Y    = OFF_DT   + 2 * MTOK * 256;
constexpr long OFF_FF   = OFF_Y    + 2 * MTOK * 256;
constexpr long OFF_W2C  = OFF_FF   + MTOK * 1024;
constexpr long OFF_WXZ  = OFF_W2C  + 24L * 256 * 256;
constexpr long OFF_BXZ  = OFF_WXZ  + 24L * 256 * 512;
constexpr long TOTAL_F  = OFF_BXZ  + 24L * 512;

__device__ float g_buf[TOTAL_F];

__device__ __forceinline__ uint32_t smem_u32(const void* p)
{
    return (uint32_t)__cvta_generic_to_shared(p);
}

// ---------------------------------------------------------------------------
// Embedding: x = LN(ids @ proj_w + proj_b)  (runs once)
// ---------------------------------------------------------------------------
__global__ void embed_ln_kernel(const float* __restrict__ ids,
                                const float* __restrict__ pw,
                                const float* __restrict__ pb,
                                const float* __restrict__ gam,
                                const float* __restrict__ bet,
                                float* __restrict__ x)
{
    __shared__ float sin[32];
    __shared__ float sred[8];
    int m = blockIdx.x, d = threadIdx.x;
    if (d < 32) sin[d] = ids[(long)m * 32 + d];
    __syncthreads();
    float v = pb[d];
#pragma unroll
    for (int e = 0; e < 32; e++)
        v = fmaf(sin[e], pw[e * 256 + d], v);
    float s = v;
#pragma unroll
    for (int o = 16; o > 0; o >>= 1) s += __shfl_xor_sync(0xffffffffu, s, o);
    if ((d & 31) == 0) sred[d >> 5] = s;
    __syncthreads();
    float mean = 0.f;
#pragma unroll
    for (int i = 0; i < 8; i++) mean += sred[i];
    mean *= (1.f / 256.f);
    float c = v - mean;
    float q = c * c;
#pragma unroll
    for (int o = 16; o > 0; o >>= 1) q += __shfl_xor_sync(0xffffffffu, q, o);
    __syncthreads();
    if ((d & 31) == 0) sred[d >> 5] = q;
    __syncthreads();
    float var = 0.f;
#pragma unroll
    for (int i = 0; i < 8; i++) var += sred[i];
    var *= (1.f / 256.f);
    x[(long)m * 256 + d] = c * rsqrtf(var + 1e-5f) * gam[d] + bet[d];
}

// ---------------------------------------------------------------------------
// Warp-level LN helper on 8 registers
// ---------------------------------------------------------------------------
__device__ __forceinline__ void warp_ln8(float* a,
                                         const float* __restrict__ gam,
                                         const float* __restrict__ bet,
                                         int lane, float* o)
{
    float s = 0.f;
#pragma unroll
    for (int i = 0; i < 8; i++) s += a[i];
#pragma unroll
    for (int off = 16; off > 0; off >>= 1) s += __shfl_xor_sync(0xffffffffu, s, off);
    float mean = s * (1.f / 256.f);
    float q = 0.f;
#pragma unroll
    for (int i = 0; i < 8; i++) {
        float c = a[i] - mean;
        q = fmaf(c, c, q);
    }
#pragma unroll
    for (int off = 16; off > 0; off >>= 1) q += __shfl_xor_sync(0xffffffffu, q, off);
    float inv = rsqrtf(q * (1.f / 256.f) + 1e-5f);
    const float4* gp = (const float4*)(gam + lane * 8);
    const float4* bp = (const float4*)(bet + lane * 8);
    float4 g0 = gp[0], g1 = gp[1], b0 = bp[0], b1 = bp[1];
    o[0] = (a[0] - mean) * inv * g0.x + b0.x;
    o[1] = (a[1] - mean) * inv * g0.y + b0.y;
    o[2] = (a[2] - mean) * inv * g0.z + b0.z;
    o[3] = (a[3] - mean) * inv * g0.w + b0.w;
    o[4] = (a[4] - mean) * inv * g1.x + b1.x;
    o[5] = (a[5] - mean) * inv * g1.y + b1.y;
    o[6] = (a[6] - mean) * inv * g1.z + b1.z;
    o[7] = (a[7] - mean) * inv * g1.w + b1.w;
}

// ---------------------------------------------------------------------------
// Warp-per-token LayerNorm (used once for the first LN1)
// ---------------------------------------------------------------------------
__global__ void __launch_bounds__(256)
ln_kernel(const float* __restrict__ in,
          const float* __restrict__ gam,
          const float* __restrict__ bet,
          float* __restrict__ out)
{
    int w = threadIdx.x >> 5, lane = threadIdx.x & 31;
    long m = (long)blockIdx.x * 8 + w;
    const float4* ip = (const float4*)(in + m * 256);
    float4 v0 = ip[lane * 2];
    float4 v1 = ip[lane * 2 + 1];
    float a[8] = {v0.x, v0.y, v0.z, v0.w, v1.x, v1.y, v1.z, v1.w};
    float o[8];
    warp_ln8(a, gam, bet, lane, o);
    float4* op = (float4*)(out + m * 256);
    op[lane * 2]     = make_float4(o[0], o[1], o[2], o[3]);
    op[lane * 2 + 1] = make_float4(o[4], o[5], o[6], o[7]);
}

// ---------------------------------------------------------------------------
// bias composition: bxz[lg][n] = sum_j ipb[l][g*128+j] * inw[lg][j][n]
// ---------------------------------------------------------------------------
__global__ void bxz_kernel(const float* __restrict__ ipb,
                           const float* __restrict__ inw,
                           float* __restrict__ bxz)
{
    int idx = blockIdx.x * 256 + threadIdx.x;   // 0 .. 24*512-1
    int lg = idx >> 9;
    int n = idx & 511;
    int l = lg >> 1, g = lg & 1;
    const float* bp = ipb + l * 256 + g * 128;
    const float* wp = inw + (long)lg * 65536 + n;
    float s = 0.f;
#pragma unroll 8
    for (int j = 0; j < 128; j++)
        s = fmaf(bp[j], wp[(long)j * 512], s);
    bxz[idx] = s;
}

// ---------------------------------------------------------------------------
// TF32 GEMM, 256 threads, 128x128 tile, BK=32, 3-stage pipeline, 1 barrier.
// lda runtime. AREV: reverse A rows within each 512-token batch for g==1.
// ---------------------------------------------------------------------------
template<int ACT, bool AREV>
__global__ void __launch_bounds__(256, 2)
tf128_kernel(const float* __restrict__ A,
             const float* __restrict__ W,
             const float* __restrict__ bias,
             float* __restrict__ C,
             int M, int N, int K, int lda,
             long sAg, long sWg, long sCg, long sBg)
{
    extern __shared__ uint32_t dyn[];
    constexpr int AW = 128 * 36;
    constexpr int SW = AW + 32 * 136;

    int g = blockIdx.z;
    A += (long)g * sAg;
    W += (long)g * sWg;
    C += (long)g * sCg;
    if (bias) bias += (long)g * sBg;
    bool rev = AREV && (g == 1);

    int tid  = threadIdx.x;
    int warp = tid >> 5;
    int lane = tid & 31;
    int wm = (warp & 1) * 64;
    int wn = (warp >> 1) * 32;
    int gID = lane >> 2;
    int tig = lane & 3;
    int rowBase = blockIdx.y * 128;
    int colBase = blockIdx.x * 128;

    const float* Wbase = W + colBase;

    auto stage = [&](int buf, int k0) {
        uint32_t* As = dyn + buf * SW;
        uint32_t* Bs = dyn + buf * SW + AW;
#pragma unroll
        for (int it = 0; it < 4; it++) {
            int f = tid + it * 256;
            int r = f >> 3, k4 = (f & 7) * 4;
            int m = rowBase + r;
            if (rev) m = (m & ~511) + 511 - (m & 511);
            asm volatile("cp.async.ca.shared.global [%0], [%1], 16;\n"
                         :: "r"(smem_u32(&As[r * 36 + k4])),
                            "l"(A + (long)m * lda + k0 + k4));
        }
#pragma unroll
        for (int it = 0; it < 4; it++) {
            int f = tid + it * 256;
            int kr = f >> 5, n4 = (f & 31) * 4;
            asm volatile("cp.async.ca.shared.global [%0], [%1], 16;\n"
                         :: "r"(smem_u32(&Bs[kr * 136 + n4])),
                            "l"(Wbase + (long)(k0 + kr) * N + n4));
        }
        asm volatile("cp.async.commit_group;\n");
    };

    float acc[4][4][4];
#pragma unroll
    for (int a = 0; a < 4; a++)
#pragma unroll
        for (int b = 0; b < 4; b++)
#pragma unroll
            for (int c = 0; c < 4; c++) acc[a][b][c] = 0.f;

    auto compute = [&](int buf) {
        uint32_t* As = dyn + buf * SW;
        uint32_t* Bs = dyn + buf * SW + AW;
#pragma unroll
        for (int ks = 0; ks < 32; ks += 8) {
            uint32_t bf[4][2];
#pragma unroll
            for (int nt = 0; nt < 4; nt++) {
                int col = wn + nt * 8 + gID;
                bf[nt][0] = Bs[(ks + tig) * 136 + col];
                bf[nt][1] = Bs[(ks + tig + 4) * 136 + col];
            }
#pragma unroll
            for (int mt = 0; mt < 4; mt++) {
                int row = wm + mt * 16 + gID;
                uint32_t a0 = As[row * 36 + ks + tig] + 0x1000u;
                uint32_t a1 = As[(row + 8) * 36 + ks + tig] + 0x1000u;
                uint32_t a2 = As[row * 36 + ks + tig + 4] + 0x1000u;
                uint32_t a3 = As[(row + 8) * 36 + ks + tig + 4] + 0x1000u;
#pragma unroll
                for (int nt = 0; nt < 4; nt++) {
                    asm volatile(
                        "mma.sync.aligned.m16n8k8.row.col.f32.tf32.tf32.f32 "
                        "{%0,%1,%2,%3}, {%4,%5,%6,%7}, {%8,%9}, {%0,%1,%2,%3};\n"
                        : "+f"(acc[mt][nt][0]), "+f"(acc[mt][nt][1]),
                          "+f"(acc[mt][nt][2]), "+f"(acc[mt][nt][3])
                        : "r"(a0), "r"(a1), "r"(a2), "r"(a3),
                          "r"(bf[nt][0]), "r"(bf[nt][1]));
                }
            }
        }
    };

    int nk = K >> 5;
    stage(0, 0);
    if (nk > 1) stage(1, 32);
    for (int ki = 0; ki < nk; ki++) {
        if (ki < nk - 1) asm volatile("cp.async.wait_group 1;\n");
        else             asm volatile("cp.async.wait_group 0;\n");
        __syncthreads();
        int kn = ki + 2;
        if (kn < nk) stage(kn % 3, kn << 5);
        compute(ki % 3);
    }

#pragma unroll
    for (int mt = 0; mt < 4; mt++) {
        int row0 = rowBase + wm + mt * 16 + gID;
#pragma unroll
        for (int nt = 0; nt < 4; nt++) {
            int col = colBase + wn + nt * 8 + tig * 2;
            float b0 = 0.f, b1 = 0.f;
            if (bias) { b0 = bias[col]; b1 = bias[col + 1]; }
            float v[4];
            v[0] = acc[mt][nt][0] + b0;
            v[1] = acc[mt][nt][1] + b1;
            v[2] = acc[mt][nt][2] + b0;
            v[3] = acc[mt][nt][3] + b1;
            if (ACT == 2) {
#pragma unroll
                for (int q = 0; q < 4; q++)
                    v[q] = 0.5f * v[q] * (1.f + erff(v[q] * 0.70710678118654752f));
            }
            *(float2*)&C[(long)row0 * N + col] = make_float2(v[0], v[1]);
            *(float2*)&C[(long)(row0 + 8) * N + col] = make_float2(v[2], v[3]);
        }
    }
}

// ---------------------------------------------------------------------------
// TF32 GEMM, 256 threads, 64x128 tile (plain store; dbc+dt fusion)
// ---------------------------------------------------------------------------
template<int ACT, bool NG, bool DTF>
__global__ void __launch_bounds__(256, 2)
tf64_kernel(const float* __restrict__ A,
            const float* __restrict__ W,
            const float* __restrict__ bias,
            float* __restrict__ C,
            int M, int N, int K,
            long sAg, long sWg, long sCg,
            const float* __restrict__ dtw,
            const float* __restrict__ dtb,
            float* __restrict__ DTout)
{
    extern __shared__ uint32_t dyn[];
    constexpr int AW = 64 * 36;
    constexpr int SW = AW + 32 * 136;

    int g = blockIdx.z;
    A += (long)g * sAg;
    W += (long)g * sWg;
    C += (long)g * sCg;
    if (DTF) {
        dtw += (long)g * 2048;
        dtb += (long)g * 256;
        DTout += (long)g * MTOK * 256;
    }

    int tid  = threadIdx.x;
    int warp = tid >> 5;
    int lane = tid & 31;
    int wm = (warp & 1) * 32;
    int wn = (warp >> 1) * 32;
    int gID = lane >> 2;
    int tig = lane & 3;
    int rowBase = blockIdx.y * 64;
    int colBase = blockIdx.x * 128;

    const float* Abase = A + (long)rowBase * K;
    const float* Wbase = W + colBase;

    if (NG) {
#pragma unroll
        for (int s = 0; s < 3; s++) {
            uint32_t* Bs = dyn + s * SW + AW;
            for (int f = tid; f < 1024; f += 256) {
                int kr = f >> 5, n4 = (f & 31) * 4;
                if (n4 + 4 > N)
                    *(uint4*)&Bs[kr * 136 + n4] = make_uint4(0, 0, 0, 0);
            }
        }
        __syncthreads();
    }

    auto stage = [&](int buf, int k0) {
        uint32_t* As = dyn + buf * SW;
        uint32_t* Bs = dyn + buf * SW + AW;
#pragma unroll
        for (int it = 0; it < 2; it++) {
            int f = tid + it * 256;
            int r = f >> 3, k4 = (f & 7) * 4;
            asm volatile("cp.async.ca.shared.global [%0], [%1], 16;\n"
                         :: "r"(smem_u32(&As[r * 36 + k4])),
                            "l"(Abase + (long)r * K + k0 + k4));
        }
#pragma unroll
        for (int it = 0; it < 4; it++) {
            int f = tid + it * 256;
            int kr = f >> 5, n4 = (f & 31) * 4;
            if (!NG || n4 + 4 <= N)
                asm volatile("cp.async.ca.shared.global [%0], [%1], 16;\n"
                             :: "r"(smem_u32(&Bs[kr * 136 + n4])),
                                "l"(Wbase + (long)(k0 + kr) * N + n4));
        }
        asm volatile("cp.async.commit_group;\n");
    };

    float acc[2][4][4];
#pragma unroll
    for (int a = 0; a < 2; a++)
#pragma unroll
        for (int b = 0; b < 4; b++)
#pragma unroll
            for (int c = 0; c < 4; c++) acc[a][b][c] = 0.f;

    auto compute = [&](int buf) {
        uint32_t* As = dyn + buf * SW;
        uint32_t* Bs = dyn + buf * SW + AW;
#pragma unroll
        for (int ks = 0; ks < 32; ks += 8) {
            uint32_t bf[4][2];
#pragma unroll
            for (int nt = 0; nt < 4; nt++) {
                int col = wn + nt * 8 + gID;
                bf[nt][0] = Bs[(ks + tig) * 136 + col];
                bf[nt][1] = Bs[(ks + tig + 4) * 136 + col];
            }
#pragma unroll
            for (int mt = 0; mt < 2; mt++) {
                int row = wm + mt * 16 + gID;
                uint32_t a0 = As[row * 36 + ks + tig] + 0x1000u;
                uint32_t a1 = As[(row + 8) * 36 + ks + tig] + 0x1000u;
                uint32_t a2 = As[row * 36 + ks + tig + 4] + 0x1000u;
                uint32_t a3 = As[(row + 8) * 36 + ks + tig + 4] + 0x1000u;
#pragma unroll
                for (int nt = 0; nt < 4; nt++) {
                    asm volatile(
                        "mma.sync.aligned.m16n8k8.row.col.f32.tf32.tf32.f32 "
                        "{%0,%1,%2,%3}, {%4,%5,%6,%7}, {%8,%9}, {%0,%1,%2,%3};\n"
                        : "+f"(acc[mt][nt][0]), "+f"(acc[mt][nt][1]),
                          "+f"(acc[mt][nt][2]), "+f"(acc[mt][nt][3])
                        : "r"(a0), "r"(a1), "r"(a2), "r"(a3),
                          "r"(bf[nt][0]), "r"(bf[nt][1]));
                }
            }
        }
    };

    int nk = K >> 5;
    stage(0, 0);
    if (nk > 1) stage(1, 32);
    for (int ki = 0; ki < nk; ki++) {
        if (ki < nk - 1) asm volatile("cp.async.wait_group 1;\n");
        else             asm volatile("cp.async.wait_group 0;\n");
        __syncthreads();
        int kn = ki + 2;
        if (kn < nk) stage(kn % 3, kn << 5);
        compute(ki % 3);
    }

#pragma unroll
    for (int mt = 0; mt < 2; mt++) {
        int row0 = rowBase + wm + mt * 16 + gID;
#pragma unroll
        for (int nt = 0; nt < 4; nt++) {
            int col = colBase + wn + nt * 8 + tig * 2;
            if (NG && col >= N) continue;
            float b0 = 0.f, b1 = 0.f;
            if (bias) { b0 = bias[col]; b1 = bias[col + 1]; }
            float v[4];
            v[0] = acc[mt][nt][0] + b0;
            v[1] = acc[mt][nt][1] + b1;
            v[2] = acc[mt][nt][2] + b0;
            v[3] = acc[mt][nt][3] + b1;
            if (ACT == 2) {
#pragma unroll
                for (int q = 0; q < 4; q++)
                    v[q] = 0.5f * v[q] * (1.f + erff(v[q] * 0.70710678118654752f));
            }
            *(float2*)&C[(long)row0 * N + col] = make_float2(v[0], v[1]);
            *(float2*)&C[(long)(row0 + 8) * N + col] = make_float2(v[2], v[3]);
        }
    }

    if (DTF) {
        float* dbs = (float*)(dyn + 3 * SW);
        if (warp < 2) {
            int col = tig * 2;
#pragma unroll
            for (int mt = 0; mt < 2; mt++) {
#pragma unroll
                for (int h = 0; h < 2; h++) {
                    int rl = wm + mt * 16 + gID + h * 8;
                    dbs[rl * 8 + col]     = acc[mt][0][h * 2];
                    dbs[rl * 8 + col + 1] = acc[mt][0][h * 2 + 1];
                }
            }
        }
        __syncthreads();
        int d = tid;
        float wreg[8];
#pragma unroll
        for (int r = 0; r < 8; r++) wreg[r] = dtw[r * 256 + d];
        float bb = dtb[d];
        float* dto = DTout + (long)rowBase * 256 + d;
        for (int r = 0; r < 64; r++) {
            float s = bb;
#pragma unroll
            for (int j = 0; j < 8; j++) s = fmaf(dbs[r * 8 + j], wreg[j], s);
            s = (s > 20.f) ? s : log1pf(expf(s));
            dto[(long)r * 256] = s;
        }
    }
}

// ---------------------------------------------------------------------------
// 32x256-tile GEMM with LN-fused epilogue. 256 threads, 8 warps (2m x 4n),
// BK=32, *** 3-stage pipeline (race-free: stage (s+2)%3 vs compute s%3) ***.
// NGRP: 1 (plain A) or 2 (accumulate groups; A rows reversed for g=1).
// LNMODE 1: out1 = LN(acc+bias+resid, g3,b3)
// LNMODE 2: o = LN(acc+bias+resid, g3,b3) -> out1; out2 = LN(o, g1,b1)
// ---------------------------------------------------------------------------
template<int LNMODE, int NGRP>
__global__ void __launch_bounds__(256, 2)
gemm256e_kernel(const float* __restrict__ A,
                const float* __restrict__ W,
                const float* __restrict__ bias,
                const float* __restrict__ resid,
                const float* __restrict__ g3,
                const float* __restrict__ b3,
                const float* __restrict__ g1,
                const float* __restrict__ b1,
                float* __restrict__ out1,
                float* __restrict__ out2,
                int K, long sAg, long sWg)
{
    extern __shared__ uint32_t dyn[];
    constexpr int AW = 32 * 36;            // 1152
    constexpr int SW = AW + 32 * 264;      // 9600 words / stage
    constexpr int N = 256;

    int tid  = threadIdx.x;
    int warp = tid >> 5;
    int lane = tid & 31;
    int wm = (warp & 1) * 16;
    int wn = (warp >> 1) * 64;
    int gID = lane >> 2;
    int tig = lane & 3;
    int rowBase = blockIdx.y * 32;

    int nkpg = K >> 5;
    int nS = NGRP * nkpg;

    auto stage = [&](int buf, int s) {
        int g = s / nkpg;
        int k0 = (s % nkpg) << 5;
        const float* Ab = A + (long)g * sAg;
        const float* Wb = W + (long)g * sWg;
        uint32_t* As = dyn + buf * SW;
        uint32_t* Bs = dyn + buf * SW + AW;
        {
            int r = tid >> 3, k4 = (tid & 7) * 4;
            int m = rowBase + r;
            if (NGRP == 2 && g == 1) m = (m & ~511) + 511 - (m & 511);
            asm volatile("cp.async.ca.shared.global [%0], [%1], 16;\n"
                         :: "r"(smem_u32(&As[r * 36 + k4])),
                            "l"(Ab + (long)m * K + k0 + k4));
        }
#pragma unroll
        for (int it = 0; it < 8; it++) {
            int f = tid + it * 256;
            int kr = f >> 6, n4 = (f & 63) * 4;
            asm volatile("cp.async.ca.shared.global [%0], [%1], 16;\n"
                         :: "r"(smem_u32(&Bs[kr * 264 + n4])),
                            "l"(Wb + (long)(k0 + kr) * N + n4));
        }
        asm volatile("cp.async.commit_group;\n");
    };

    float acc[8][4];
#pragma unroll
    for (int b = 0; b < 8; b++)
#pragma unroll
        for (int c = 0; c < 4; c++) acc[b][c] = 0.f;

    auto compute = [&](int buf) {
        uint32_t* As = dyn + buf * SW;
        uint32_t* Bs = dyn + buf * SW + AW;
#pragma unroll
        for (int ks = 0; ks < 32; ks += 8) {
            int row = wm + gID;
            uint32_t a0 = As[row * 36 + ks + tig] + 0x1000u;
            uint32_t a1 = As[(row + 8) * 36 + ks + tig] + 0x1000u;
            uint32_t a2 = As[row * 36 + ks + tig + 4] + 0x1000u;
            uint32_t a3 = As[(row + 8) * 36 + ks + tig + 4] + 0x1000u;
#pragma unroll
            for (int nt = 0; nt < 8; nt++) {
                int col = wn + nt * 8 + gID;
                uint32_t bf0 = Bs[(ks + tig) * 264 + col];
                uint32_t bf1 = Bs[(ks + tig + 4) * 264 + col];
                asm volatile(
                    "mma.sync.aligned.m16n8k8.row.col.f32.tf32.tf32.f32 "
                    "{%0,%1,%2,%3}, {%4,%5,%6,%7}, {%8,%9}, {%0,%1,%2,%3};\n"
                    : "+f"(acc[nt][0]), "+f"(acc[nt][1]),
                      "+f"(acc[nt][2]), "+f"(acc[nt][3])
                    : "r"(a0), "r"(a1), "r"(a2), "r"(a3),
                      "r"(bf0), "r"(bf1));
            }
        }
    };

    // 3-stage ring: stage (s+2)%3 while computing s%3 — no buffer overlap
    stage(0, 0);
    if (nS > 1) stage(1, 1);
    for (int s = 0; s < nS; s++) {
        if (s < nS - 1) asm volatile("cp.async.wait_group 1;\n");
        else            asm volatile("cp.async.wait_group 0;\n");
        __syncthreads();
        int sn = s + 2;
        if (sn < nS) stage(sn % 3, sn);
        compute(s % 3);
        __syncthreads();
    }

    // epilogue: stage acc+bias into smem scratch, then warp-per-token LN
    float* scr = (float*)dyn;           // [32][260]
    {
        int row0 = wm + gID;
#pragma unroll
        for (int nt = 0; nt < 8; nt++) {
            int col = wn + nt * 8 + tig * 2;
            float b0 = bias[col], b1 = bias[col + 1];
            scr[row0 * 260 + col]       = acc[nt][0] + b0;
            scr[row0 * 260 + col + 1]   = acc[nt][1] + b1;
            scr[(row0 + 8) * 260 + col]     = acc[nt][2] + b0;
            scr[(row0 + 8) * 260 + col + 1] = acc[nt][3] + b1;
        }
    }
    __syncthreads();
#pragma unroll
    for (int rr = 0; rr < 4; rr++) {
        int r = warp * 4 + rr;
        long m = rowBase + r;
        float a[8], o[8];
        const float* rp = resid + m * 256 + lane * 8;
#pragma unroll
        for (int i = 0; i < 8; i++)
            a[i] = scr[r * 260 + lane * 8 + i] + rp[i];
        warp_ln8(a, g3, b3, lane, o);
        float4* o1 = (float4*)(out1 + m * 256 + lane * 8);
        o1[0] = make_float4(o[0], o[1], o[2], o[3]);
        o1[1] = make_float4(o[4], o[5], o[6], o[7]);
        if (LNMODE == 2 && out2) {
            float o2[8];
            warp_ln8(o, g1, b1, lane, o2);
            float4* p2 = (float4*)(out2 + m * 256 + lane * 8);
            p2[0] = make_float4(o2[0], o2[1], o2[2], o2[3]);
            p2[1] = make_float4(o2[4], o2[5], o2[6], o2[7]);
        }
    }
}

// ---------------------------------------------------------------------------
// depthwise causal conv (K=4) + bias + silu; 4 t-outputs per thread
// ---------------------------------------------------------------------------
__global__ void conv_silu_kernel(const float* __restrict__ xz,
                                 const float* __restrict__ convw,
                                 const float* __restrict__ convb,
                                 float* __restrict__ xc)
{
    long i = (long)blockIdx.x * 256 + threadIdx.x;
    if (i >= 2 * MTOK * 64) return;
    int d = (int)(i & 255);
    long q = i >> 8;
    int t0 = (int)(q & 127) * 4;
    int b  = (int)((q >> 7) & 15);
    int g  = (int)(q >> 11);

    const float4 w4 = *(const float4*)(convw + ((long)g * 256 + d) * 4);
    float bias = convb[(long)g * 256 + d];

    long mrow = (long)g * MTOK + (long)b * 512 + t0;
    const float* xp = xz + mrow * 512 + d;
    float xv[7];
#pragma unroll
    for (int j = 0; j < 7; j++) {
        int t = t0 - 3 + j;
        xv[j] = (t >= 0) ? xp[(long)(j - 3) * 512] : 0.f;
    }
    float* op = xc + mrow * 256 + d;
#pragma unroll
    for (int j = 0; j < 4; j++) {
        float acc = bias;
        acc = fmaf(xv[j],     w4.x, acc);
        acc = fmaf(xv[j + 1], w4.y, acc);
        acc = fmaf(xv[j + 2], w4.z, acc);
        acc = fmaf(xv[j + 3], w4.w, acc);
        op[(long)j * 256] = acc / (1.f + __expf(-acc));
    }
}

// ---------------------------------------------------------------------------
// Selective scan, 8 lanes per (g,b,d) group, 2 states per lane, pipelined.
// ---------------------------------------------------------------------------
__global__ void __launch_bounds__(256)
scan_kernel(const float* __restrict__ dt,
            const float* __restrict__ xc,
            const float* __restrict__ dbc,
            const float* __restrict__ xz,
            const float* __restrict__ alog,
            const float* __restrict__ dpar,
            float* __restrict__ y)
{
    int gidx = blockIdx.x * 32 + (threadIdx.x >> 3);
    int li = threadIdx.x & 7;
    int g = gidx >> 12;
    int b = (gidx >> 8) & 15;
    int d = gidx & 255;

    const float2 al = *(const float2*)&alog[((long)(g * 256 + d)) * 16 + li * 2];
    const float L2E = 1.4426950408889634f;
    float A0 = -__expf(al.x) * L2E;
    float A1 = -__expf(al.y) * L2E;
    float dp = dpar[(long)g * 256 + d];

    long mbase = (long)g * MTOK + (long)b * 512;
    const float* dtp = dt + mbase * 256 + d;
    const float* xcp = xc + mbase * 256 + d;
    const float* dbp = dbc + mbase * 40;
    const float* zp  = xz + mbase * 512 + 256 + d;
    float* yp = y + mbase * 256 + d;

    float h0 = 0.f, h1 = 0.f;

    float dtv_n = dtp[0];
    float xv_n  = xcp[0];
    float z_n   = zp[0];
    float2 B_n  = *(const float2*)&dbp[8 + li * 2];
    float2 C_n  = *(const float2*)&dbp[24 + li * 2];

    for (int t = 0; t < 512; t++) {
        float dtv = dtv_n, xv = xv_n, z = z_n;
        float2 Bv = B_n, Cv = C_n;
        long tn = (t + 1 < 512) ? t + 1 : 511;
        dtv_n = dtp[tn * 256];
        xv_n  = xcp[tn * 256];
        z_n   = zp[tn * 512];
        B_n   = *(const float2*)&dbp[tn * 40 + 8 + li * 2];
        C_n   = *(const float2*)&dbp[tn * 40 + 24 + li * 2];

        float dx = dtv * xv;
        h0 = exp2f(dtv * A0) * h0 + dx * Bv.x;
        h1 = exp2f(dtv * A1) * h1 + dx * Bv.y;
        float p = h0 * Cv.x + h1 * Cv.y;
        p += __shfl_xor_sync(0xffffffffu, p, 4);
        p += __shfl_xor_sync(0xffffffffu, p, 2);
        p += __shfl_xor_sync(0xffffffffu, p, 1);
        if (li == 0) {
            float sz = z / (1.f + __expf(-z));
            yp[(long)t * 256] = (p + dp * xv) * sz;
        }
    }
}

// ---------------------------------------------------------------------------
// Launch helpers
// ---------------------------------------------------------------------------
constexpr int SMEM128 = 3 * (128 * 36 + 32 * 136) * 4;
constexpr int SMEM64  = 3 * (64 * 36 + 32 * 136) * 4 + 2048;
constexpr int SMEM256E = 3 * (32 * 36 + 32 * 264) * 4;        // 115200 B

template<int ACT, bool AREV>
static void launch_tf128(const float* A, const float* W, const float* bias, float* C,
                         int M, int N, int K, int lda, int G,
                         long sAg, long sWg, long sCg, long sBg)
{
    cudaFuncSetAttribute(tf128_kernel<ACT, AREV>,
                         cudaFuncAttributeMaxDynamicSharedMemorySize, SMEM128);
    dim3 grid(N / 128, M / 128, G);
    tf128_kernel<ACT, AREV><<<grid, 256, SMEM128>>>(A, W, bias, C, M, N, K, lda,
                                                    sAg, sWg, sCg, sBg);
}

template<int ACT, bool NG, bool DTF>
static void launch_tf64(const float* A, const float* W, const float* bias, float* C,
                        int M, int N, int K, int G,
                        long sAg, long sWg, long sCg,
                        const float* dtw = nullptr, const float* dtb = nullptr,
                        float* DTout = nullptr)
{
    cudaFuncSetAttribute(tf64_kernel<ACT, NG, DTF>,
                         cudaFuncAttributeMaxDynamicSharedMemorySize, SMEM64);
    dim3 grid((N + 127) / 128, M / 64, G);
    tf64_kernel<ACT, NG, DTF><<<grid, 256, SMEM64>>>(
        A, W, bias, C, M, N, K, sAg, sWg, sCg, dtw, dtb, DTout);
}

template<int LNMODE, int NGRP>
static void launch_g256e(const float* A, const float* W, const float* bias,
                         const float* resid,
                         const float* g3, const float* b3,
                         const float* g1, const float* b1,
                         float* out1, float* out2,
                         int K, long sAg, long sWg)
{
    cudaFuncSetAttribute(gemm256e_kernel<LNMODE, NGRP>,
                         cudaFuncAttributeMaxDynamicSharedMemorySize, SMEM256E);
    dim3 grid(1, (int)(MTOK / 32), 1);
    gemm256e_kernel<LNMODE, NGRP><<<grid, 256, SMEM256E>>>(
        A, W, bias, resid, g3, b3, g1, b1, out1, out2, K, sAg, sWg);
}

extern "C" void kernel_launch(void* const* d_in, const int* in_sizes, int n_in,
                              void* d_out, int out_size)
{
    const float* input_ids = (const float*)d_in[0];
    const float* proj_w    = (const float*)d_in[1];
    const float* proj_b    = (const float*)d_in[2];
    const float* ln0_g     = (const float*)d_in[3];
    const float* ln0_b     = (const float*)d_in[4];
    const float* ln1_g     = (const float*)d_in[5];
    const float* ln1_b     = (const float*)d_in[6];
    const float* ip_w      = (const float*)d_in[7];
    const float* ip_b      = (const float*)d_in[8];
    const float* s_inw     = (const float*)d_in[9];
    const float* s_convw   = (const float*)d_in[10];
    const float* s_convb   = (const float*)d_in[11];
    const float* s_xw      = (const float*)d_in[12];
    const float* s_dtw     = (const float*)d_in[13];
    const float* s_dtb     = (const float*)d_in[14];
    const float* s_alog    = (const float*)d_in[15];
    const float* s_d       = (const float*)d_in[16];
    const float* s_outw    = (const float*)d_in[17];
    const float* op_w      = (const float*)d_in[18];
    const float* op_b      = (const float*)d_in[19];
    const float* ln2_g     = (const float*)d_in[20];
    const float* ln2_b     = (const float*)d_in[21];
    const float* f_w1      = (const float*)d_in[22];
    const float* f_b1      = (const float*)d_in[23];
    const float* f_w2      = (const float*)d_in[24];
    const float* f_b2      = (const float*)d_in[25];
    const float* ln3_g     = (const float*)d_in[26];
    const float* ln3_b     = (const float*)d_in[27];

    float* base = nullptr;
    cudaGetSymbolAddress((void**)&base, g_buf);

    float* X    = base + OFF_X;
    float* LNb  = base + OFF_LN;
    float* XZ   = base + OFF_XZ;
    float* XC   = base + OFF_XC;
    float* DBC  = base + OFF_DBC;
    float* DT   = base + OFF_DT;
    float* Y    = base + OFF_Y;
    float* FF   = base + OFF_FF;
    float* W2C  = base + OFF_W2C;
    float* WXZ  = base + OFF_WXZ;
    float* BXZ  = base + OFF_BXZ;

    const int M = (int)MTOK;
    const int CONV_BLOCKS = (int)(2 * MTOK * 64 / 256);
    const int LN_BLOCKS = (int)(MTOK / 8);

    // --- precompute composed weights -------------------------------------
    // W2C[l][g] = outw[l][g] @ opw[l][g-part]
    launch_tf64<0, false, false>(s_outw, op_w, nullptr, W2C,
                                 256, 256, 128, 24, 32768, 32768, 65536);
    // WXZ[l][g] = ipw[l][:, g*128:+128] @ inw[l][g]
    for (int g = 0; g < 2; g++) {
        launch_tf128<0, false>(ip_w + g * 128, s_inw + (long)g * 65536, nullptr,
                               WXZ + (long)g * 131072,
                               256, 512, 128, 256, 12,
                               65536, 131072, 262144, 0);
    }
    // BXZ[l][g] = ipb-slice @ inw[l][g]
    bxz_kernel<<<48, 256>>>(ip_b, s_inw, BXZ);

    // --- embedding + first LN1 -------------------------------------------
    embed_ln_kernel<<<M, 256>>>(input_ids, proj_w, proj_b, ln0_g, ln0_b, X);
    ln_kernel<<<LN_BLOCKS, 256>>>(X, ln1_g, ln1_b, LNb);

    for (int l = 0; l < 12; l++) {
        // xz = LN1[rev_g] @ WXZ[l][g] + BXZ[l][g]
        launch_tf128<0, true>(LNb, WXZ + (long)l * 262144, BXZ + (long)l * 1024, XZ,
                              M, 512, 256, 256, 2,
                              0, 131072, MTOK * 512, 512);
        // conv + silu
        conv_silu_kernel<<<CONV_BLOCKS, 256>>>(XZ, s_convw + (long)l * 2 * 256 * 4,
                                               s_convb + (long)l * 2 * 256, XC);
        // dbc = xc @ xw (N=40 guarded) + fused dt
        launch_tf64<0, true, true>(XC, s_xw + (long)l * 2 * 256 * 40, nullptr, DBC,
                                   M, 40, 256, 2, MTOK * 256, 256 * 40, MTOK * 40,
                                   s_dtw + (long)l * 2 * 8 * 256,
                                   s_dtb + (long)l * 2 * 256, DT);
        // selective scan + fused silu(z) gate
        scan_kernel<<<256, 256>>>(DT, XC, DBC, XZ,
                                  s_alog + (long)l * 2 * 256 * 16,
                                  s_d + (long)l * 2 * 256, Y);
        // fused outw∘opw projection + op_b + residual + LN2 -> X
        launch_g256e<1, 2>(Y, W2C + (long)l * 2 * 65536, op_b + l * 256,
                           X, ln2_g + l * 256, ln2_b + l * 256,
                           nullptr, nullptr, X, nullptr,
                           256, MTOK * 256, 65536);
        // ff = gelu(x @ w1 + b1)
        launch_tf128<2, false>(X, f_w1 + (long)l * 256 * 1024, f_b1 + l * 1024, FF,
                               M, 1024, 256, 256, 1, 0, 0, 0, 0);
        // f = ff @ w2 + b2 + residual X + LN3 -> dst ; LN1(next) -> LNb
        float* dst = (l == 11) ? (float*)d_out : X;
        float* lnb = (l == 11) ? nullptr : LNb;
        const float* g1 = ln1_g + (l + 1 < 12 ? (l + 1) * 256 : 0);
        const float* b1 = ln1_b + (l + 1 < 12 ? (l + 1) * 256 : 0);
        launch_g256e<2, 1>(FF, f_w2 + (long)l * 1024 * 256, f_b2 + l * 256,
                           X, ln3_g + l * 256, ln3_b + l * 256,
                           g1, b1, dst, lnb,
                           1024, 0, 0);
    }
}

// round 14
// speedup vs baseline: 1.0799x; 1.0799x over previous
#include <cuda_runtime.h>
#include <math.h>
#include <stdint.h>

constexpr long MTOK  = 16 * 512;     // 8192 tokens

// ---------------------------------------------------------------------------
// Scratch arena
// ---------------------------------------------------------------------------
constexpr long OFF_X    = 0;
constexpr long OFF_LN   = OFF_X    + MTOK * 256;
constexpr long OFF_XZ   = OFF_LN   + MTOK * 256;
constexpr long OFF_XC   = OFF_XZ   + 2 * MTOK * 512;
constexpr long OFF_DBC  = OFF_XC   + 2 * MTOK * 256;
constexpr long OFF_DT   = OFF_DBC  + 2 * MTOK * 40;
constexpr long OFF_Y    = OFF_DT   + 2 * MTOK * 256;
constexpr long OFF_FF   = OFF_Y    + 2 * MTOK * 256;
constexpr long OFF_W2C  = OFF_FF   + MTOK * 1024;
constexpr long OFF_WXZ  = OFF_W2C  + 24L * 256 * 256;
constexpr long OFF_BXZ  = OFF_WXZ  + 24L * 256 * 512;
constexpr long TOTAL_F  = OFF_BXZ  + 24L * 512;

__device__ float g_buf[TOTAL_F];

__device__ __forceinline__ uint32_t smem_u32(const void* p)
{
    return (uint32_t)__cvta_generic_to_shared(p);
}

// ---------------------------------------------------------------------------
// Embedding: x = LN(ids @ proj_w + proj_b)  (runs once)
// ---------------------------------------------------------------------------
__global__ void embed_ln_kernel(const float* __restrict__ ids,
                                const float* __restrict__ pw,
                                const float* __restrict__ pb,
                                const float* __restrict__ gam,
                                const float* __restrict__ bet,
                                float* __restrict__ x)
{
    __shared__ float sin[32];
    __shared__ float sred[8];
    int m = blockIdx.x, d = threadIdx.x;
    if (d < 32) sin[d] = ids[(long)m * 32 + d];
    __syncthreads();
    float v = pb[d];
#pragma unroll
    for (int e = 0; e < 32; e++)
        v = fmaf(sin[e], pw[e * 256 + d], v);
    float s = v;
#pragma unroll
    for (int o = 16; o > 0; o >>= 1) s += __shfl_xor_sync(0xffffffffu, s, o);
    if ((d & 31) == 0) sred[d >> 5] = s;
    __syncthreads();
    float mean = 0.f;
#pragma unroll
    for (int i = 0; i < 8; i++) mean += sred[i];
    mean *= (1.f / 256.f);
    float c = v - mean;
    float q = c * c;
#pragma unroll
    for (int o = 16; o > 0; o >>= 1) q += __shfl_xor_sync(0xffffffffu, q, o);
    __syncthreads();
    if ((d & 31) == 0) sred[d >> 5] = q;
    __syncthreads();
    float var = 0.f;
#pragma unroll
    for (int i = 0; i < 8; i++) var += sred[i];
    var *= (1.f / 256.f);
    x[(long)m * 256 + d] = c * rsqrtf(var + 1e-5f) * gam[d] + bet[d];
}

// ---------------------------------------------------------------------------
// Warp-level LN helper on 8 registers
// ---------------------------------------------------------------------------
__device__ __forceinline__ void warp_ln8(float* a,
                                         const float* __restrict__ gam,
                                         const float* __restrict__ bet,
                                         int lane, float* o)
{
    float s = 0.f;
#pragma unroll
    for (int i = 0; i < 8; i++) s += a[i];
#pragma unroll
    for (int off = 16; off > 0; off >>= 1) s += __shfl_xor_sync(0xffffffffu, s, off);
    float mean = s * (1.f / 256.f);
    float q = 0.f;
#pragma unroll
    for (int i = 0; i < 8; i++) {
        float c = a[i] - mean;
        q = fmaf(c, c, q);
    }
#pragma unroll
    for (int off = 16; off > 0; off >>= 1) q += __shfl_xor_sync(0xffffffffu, q, off);
    float inv = rsqrtf(q * (1.f / 256.f) + 1e-5f);
    const float4* gp = (const float4*)(gam + lane * 8);
    const float4* bp = (const float4*)(bet + lane * 8);
    float4 g0 = gp[0], g1 = gp[1], b0 = bp[0], b1 = bp[1];
    o[0] = (a[0] - mean) * inv * g0.x + b0.x;
    o[1] = (a[1] - mean) * inv * g0.y + b0.y;
    o[2] = (a[2] - mean) * inv * g0.z + b0.z;
    o[3] = (a[3] - mean) * inv * g0.w + b0.w;
    o[4] = (a[4] - mean) * inv * g1.x + b1.x;
    o[5] = (a[5] - mean) * inv * g1.y + b1.y;
    o[6] = (a[6] - mean) * inv * g1.z + b1.z;
    o[7] = (a[7] - mean) * inv * g1.w + b1.w;
}

// ---------------------------------------------------------------------------
// Warp-per-token LayerNorm (used once for the first LN1)
// ---------------------------------------------------------------------------
__global__ void __launch_bounds__(256)
ln_kernel(const float* __restrict__ in,
          const float* __restrict__ gam,
          const float* __restrict__ bet,
          float* __restrict__ out)
{
    int w = threadIdx.x >> 5, lane = threadIdx.x & 31;
    long m = (long)blockIdx.x * 8 + w;
    const float4* ip = (const float4*)(in + m * 256);
    float4 v0 = ip[lane * 2];
    float4 v1 = ip[lane * 2 + 1];
    float a[8] = {v0.x, v0.y, v0.z, v0.w, v1.x, v1.y, v1.z, v1.w};
    float o[8];
    warp_ln8(a, gam, bet, lane, o);
    float4* op = (float4*)(out + m * 256);
    op[lane * 2]     = make_float4(o[0], o[1], o[2], o[3]);
    op[lane * 2 + 1] = make_float4(o[4], o[5], o[6], o[7]);
}

// ---------------------------------------------------------------------------
// bias composition: bxz[lg][n] = sum_j ipb[l][g*128+j] * inw[lg][j][n]
// ---------------------------------------------------------------------------
__global__ void bxz_kernel(const float* __restrict__ ipb,
                           const float* __restrict__ inw,
                           float* __restrict__ bxz)
{
    int idx = blockIdx.x * 256 + threadIdx.x;   // 0 .. 24*512-1
    int lg = idx >> 9;
    int n = idx & 511;
    int l = lg >> 1, g = lg & 1;
    const float* bp = ipb + l * 256 + g * 128;
    const float* wp = inw + (long)lg * 65536 + n;
    float s = 0.f;
#pragma unroll 8
    for (int j = 0; j < 128; j++)
        s = fmaf(bp[j], wp[(long)j * 512], s);
    bxz[idx] = s;
}

// ---------------------------------------------------------------------------
// TF32 GEMM, 256 threads, 128x128 tile, BK=32, 3-stage pipeline, 1 barrier.
// lda runtime. AREV: reverse A rows within each 512-token batch for g==1.
// ---------------------------------------------------------------------------
template<int ACT, bool AREV>
__global__ void __launch_bounds__(256, 2)
tf128_kernel(const float* __restrict__ A,
             const float* __restrict__ W,
             const float* __restrict__ bias,
             float* __restrict__ C,
             int M, int N, int K, int lda,
             long sAg, long sWg, long sCg, long sBg)
{
    extern __shared__ uint32_t dyn[];
    constexpr int AW = 128 * 36;
    constexpr int SW = AW + 32 * 136;

    int g = blockIdx.z;
    A += (long)g * sAg;
    W += (long)g * sWg;
    C += (long)g * sCg;
    if (bias) bias += (long)g * sBg;
    bool rev = AREV && (g == 1);

    int tid  = threadIdx.x;
    int warp = tid >> 5;
    int lane = tid & 31;
    int wm = (warp & 1) * 64;
    int wn = (warp >> 1) * 32;
    int gID = lane >> 2;
    int tig = lane & 3;
    int rowBase = blockIdx.y * 128;
    int colBase = blockIdx.x * 128;

    const float* Wbase = W + colBase;

    auto stage = [&](int buf, int k0) {
        uint32_t* As = dyn + buf * SW;
        uint32_t* Bs = dyn + buf * SW + AW;
#pragma unroll
        for (int it = 0; it < 4; it++) {
            int f = tid + it * 256;
            int r = f >> 3, k4 = (f & 7) * 4;
            int m = rowBase + r;
            if (rev) m = (m & ~511) + 511 - (m & 511);
            asm volatile("cp.async.ca.shared.global [%0], [%1], 16;\n"
                         :: "r"(smem_u32(&As[r * 36 + k4])),
                            "l"(A + (long)m * lda + k0 + k4));
        }
#pragma unroll
        for (int it = 0; it < 4; it++) {
            int f = tid + it * 256;
            int kr = f >> 5, n4 = (f & 31) * 4;
            asm volatile("cp.async.ca.shared.global [%0], [%1], 16;\n"
                         :: "r"(smem_u32(&Bs[kr * 136 + n4])),
                            "l"(Wbase + (long)(k0 + kr) * N + n4));
        }
        asm volatile("cp.async.commit_group;\n");
    };

    float acc[4][4][4];
#pragma unroll
    for (int a = 0; a < 4; a++)
#pragma unroll
        for (int b = 0; b < 4; b++)
#pragma unroll
            for (int c = 0; c < 4; c++) acc[a][b][c] = 0.f;

    auto compute = [&](int buf) {
        uint32_t* As = dyn + buf * SW;
        uint32_t* Bs = dyn + buf * SW + AW;
#pragma unroll
        for (int ks = 0; ks < 32; ks += 8) {
            uint32_t bf[4][2];
#pragma unroll
            for (int nt = 0; nt < 4; nt++) {
                int col = wn + nt * 8 + gID;
                bf[nt][0] = Bs[(ks + tig) * 136 + col];
                bf[nt][1] = Bs[(ks + tig + 4) * 136 + col];
            }
#pragma unroll
            for (int mt = 0; mt < 4; mt++) {
                int row = wm + mt * 16 + gID;
                uint32_t a0 = As[row * 36 + ks + tig] + 0x1000u;
                uint32_t a1 = As[(row + 8) * 36 + ks + tig] + 0x1000u;
                uint32_t a2 = As[row * 36 + ks + tig + 4] + 0x1000u;
                uint32_t a3 = As[(row + 8) * 36 + ks + tig + 4] + 0x1000u;
#pragma unroll
                for (int nt = 0; nt < 4; nt++) {
                    asm volatile(
                        "mma.sync.aligned.m16n8k8.row.col.f32.tf32.tf32.f32 "
                        "{%0,%1,%2,%3}, {%4,%5,%6,%7}, {%8,%9}, {%0,%1,%2,%3};\n"
                        : "+f"(acc[mt][nt][0]), "+f"(acc[mt][nt][1]),
                          "+f"(acc[mt][nt][2]), "+f"(acc[mt][nt][3])
                        : "r"(a0), "r"(a1), "r"(a2), "r"(a3),
                          "r"(bf[nt][0]), "r"(bf[nt][1]));
                }
            }
        }
    };

    int nk = K >> 5;
    stage(0, 0);
    if (nk > 1) stage(1, 32);
    for (int ki = 0; ki < nk; ki++) {
        if (ki < nk - 1) asm volatile("cp.async.wait_group 1;\n");
        else             asm volatile("cp.async.wait_group 0;\n");
        __syncthreads();
        int kn = ki + 2;
        if (kn < nk) stage(kn % 3, kn << 5);
        compute(ki % 3);
    }

#pragma unroll
    for (int mt = 0; mt < 4; mt++) {
        int row0 = rowBase + wm + mt * 16 + gID;
#pragma unroll
        for (int nt = 0; nt < 4; nt++) {
            int col = colBase + wn + nt * 8 + tig * 2;
            float b0 = 0.f, b1 = 0.f;
            if (bias) { b0 = bias[col]; b1 = bias[col + 1]; }
            float v[4];
            v[0] = acc[mt][nt][0] + b0;
            v[1] = acc[mt][nt][1] + b1;
            v[2] = acc[mt][nt][2] + b0;
            v[3] = acc[mt][nt][3] + b1;
            if (ACT == 2) {
#pragma unroll
                for (int q = 0; q < 4; q++)
                    v[q] = 0.5f * v[q] * (1.f + erff(v[q] * 0.70710678118654752f));
            }
            *(float2*)&C[(long)row0 * N + col] = make_float2(v[0], v[1]);
            *(float2*)&C[(long)(row0 + 8) * N + col] = make_float2(v[2], v[3]);
        }
    }
}

// ---------------------------------------------------------------------------
// TF32 GEMM, 256 threads, 64x128 tile (plain store; dbc+dt fusion)
// ---------------------------------------------------------------------------
template<int ACT, bool NG, bool DTF>
__global__ void __launch_bounds__(256, 2)
tf64_kernel(const float* __restrict__ A,
            const float* __restrict__ W,
            const float* __restrict__ bias,
            float* __restrict__ C,
            int M, int N, int K,
            long sAg, long sWg, long sCg,
            const float* __restrict__ dtw,
            const float* __restrict__ dtb,
            float* __restrict__ DTout)
{
    extern __shared__ uint32_t dyn[];
    constexpr int AW = 64 * 36;
    constexpr int SW = AW + 32 * 136;

    int g = blockIdx.z;
    A += (long)g * sAg;
    W += (long)g * sWg;
    C += (long)g * sCg;
    if (DTF) {
        dtw += (long)g * 2048;
        dtb += (long)g * 256;
        DTout += (long)g * MTOK * 256;
    }

    int tid  = threadIdx.x;
    int warp = tid >> 5;
    int lane = tid & 31;
    int wm = (warp & 1) * 32;
    int wn = (warp >> 1) * 32;
    int gID = lane >> 2;
    int tig = lane & 3;
    int rowBase = blockIdx.y * 64;
    int colBase = blockIdx.x * 128;

    const float* Abase = A + (long)rowBase * K;
    const float* Wbase = W + colBase;

    if (NG) {
#pragma unroll
        for (int s = 0; s < 3; s++) {
            uint32_t* Bs = dyn + s * SW + AW;
            for (int f = tid; f < 1024; f += 256) {
                int kr = f >> 5, n4 = (f & 31) * 4;
                if (n4 + 4 > N)
                    *(uint4*)&Bs[kr * 136 + n4] = make_uint4(0, 0, 0, 0);
            }
        }
        __syncthreads();
    }

    auto stage = [&](int buf, int k0) {
        uint32_t* As = dyn + buf * SW;
        uint32_t* Bs = dyn + buf * SW + AW;
#pragma unroll
        for (int it = 0; it < 2; it++) {
            int f = tid + it * 256;
            int r = f >> 3, k4 = (f & 7) * 4;
            asm volatile("cp.async.ca.shared.global [%0], [%1], 16;\n"
                         :: "r"(smem_u32(&As[r * 36 + k4])),
                            "l"(Abase + (long)r * K + k0 + k4));
        }
#pragma unroll
        for (int it = 0; it < 4; it++) {
            int f = tid + it * 256;
            int kr = f >> 5, n4 = (f & 31) * 4;
            if (!NG || n4 + 4 <= N)
                asm volatile("cp.async.ca.shared.global [%0], [%1], 16;\n"
                             :: "r"(smem_u32(&Bs[kr * 136 + n4])),
                                "l"(Wbase + (long)(k0 + kr) * N + n4));
        }
        asm volatile("cp.async.commit_group;\n");
    };

    float acc[2][4][4];
#pragma unroll
    for (int a = 0; a < 2; a++)
#pragma unroll
        for (int b = 0; b < 4; b++)
#pragma unroll
            for (int c = 0; c < 4; c++) acc[a][b][c] = 0.f;

    auto compute = [&](int buf) {
        uint32_t* As = dyn + buf * SW;
        uint32_t* Bs = dyn + buf * SW + AW;
#pragma unroll
        for (int ks = 0; ks < 32; ks += 8) {
            uint32_t bf[4][2];
#pragma unroll
            for (int nt = 0; nt < 4; nt++) {
                int col = wn + nt * 8 + gID;
                bf[nt][0] = Bs[(ks + tig) * 136 + col];
                bf[nt][1] = Bs[(ks + tig + 4) * 136 + col];
            }
#pragma unroll
            for (int mt = 0; mt < 2; mt++) {
                int row = wm + mt * 16 + gID;
                uint32_t a0 = As[row * 36 + ks + tig] + 0x1000u;
                uint32_t a1 = As[(row + 8) * 36 + ks + tig] + 0x1000u;
                uint32_t a2 = As[row * 36 + ks + tig + 4] + 0x1000u;
                uint32_t a3 = As[(row + 8) * 36 + ks + tig + 4] + 0x1000u;
#pragma unroll
                for (int nt = 0; nt < 4; nt++) {
                    asm volatile(
                        "mma.sync.aligned.m16n8k8.row.col.f32.tf32.tf32.f32 "
                        "{%0,%1,%2,%3}, {%4,%5,%6,%7}, {%8,%9}, {%0,%1,%2,%3};\n"
                        : "+f"(acc[mt][nt][0]), "+f"(acc[mt][nt][1]),
                          "+f"(acc[mt][nt][2]), "+f"(acc[mt][nt][3])
                        : "r"(a0), "r"(a1), "r"(a2), "r"(a3),
                          "r"(bf[nt][0]), "r"(bf[nt][1]));
                }
            }
        }
    };

    int nk = K >> 5;
    stage(0, 0);
    if (nk > 1) stage(1, 32);
    for (int ki = 0; ki < nk; ki++) {
        if (ki < nk - 1) asm volatile("cp.async.wait_group 1;\n");
        else             asm volatile("cp.async.wait_group 0;\n");
        __syncthreads();
        int kn = ki + 2;
        if (kn < nk) stage(kn % 3, kn << 5);
        compute(ki % 3);
    }

#pragma unroll
    for (int mt = 0; mt < 2; mt++) {
        int row0 = rowBase + wm + mt * 16 + gID;
#pragma unroll
        for (int nt = 0; nt < 4; nt++) {
            int col = colBase + wn + nt * 8 + tig * 2;
            if (NG && col >= N) continue;
            float b0 = 0.f, b1 = 0.f;
            if (bias) { b0 = bias[col]; b1 = bias[col + 1]; }
            float v[4];
            v[0] = acc[mt][nt][0] + b0;
            v[1] = acc[mt][nt][1] + b1;
            v[2] = acc[mt][nt][2] + b0;
            v[3] = acc[mt][nt][3] + b1;
            if (ACT == 2) {
#pragma unroll
                for (int q = 0; q < 4; q++)
                    v[q] = 0.5f * v[q] * (1.f + erff(v[q] * 0.70710678118654752f));
            }
            *(float2*)&C[(long)row0 * N + col] = make_float2(v[0], v[1]);
            *(float2*)&C[(long)(row0 + 8) * N + col] = make_float2(v[2], v[3]);
        }
    }

    if (DTF) {
        float* dbs = (float*)(dyn + 3 * SW);
        if (warp < 2) {
            int col = tig * 2;
#pragma unroll
            for (int mt = 0; mt < 2; mt++) {
#pragma unroll
                for (int h = 0; h < 2; h++) {
                    int rl = wm + mt * 16 + gID + h * 8;
                    dbs[rl * 8 + col]     = acc[mt][0][h * 2];
                    dbs[rl * 8 + col + 1] = acc[mt][0][h * 2 + 1];
                }
            }
        }
        __syncthreads();
        int d = tid;
        float wreg[8];
#pragma unroll
        for (int r = 0; r < 8; r++) wreg[r] = dtw[r * 256 + d];
        float bb = dtb[d];
        float* dto = DTout + (long)rowBase * 256 + d;
        for (int r = 0; r < 64; r++) {
            float s = bb;
#pragma unroll
            for (int j = 0; j < 8; j++) s = fmaf(dbs[r * 8 + j], wreg[j], s);
            s = (s > 20.f) ? s : log1pf(expf(s));
            dto[(long)r * 256] = s;
        }
    }
}

// ---------------------------------------------------------------------------
// 64x256-tile GEMM with LN-fused epilogue. 256 threads, 8 warps (2m x 4n,
// each warp 32x64 -> 1.5 LDS/MMA). BK=32, 2-stage double-buffer (R6-proven
// pattern: stage next, wait 1, sync, compute cur, sync).
// NGRP: 1 (plain A) or 2 (accumulate groups; A rows reversed for g=1).
// LNMODE 1: out1 = LN(acc+bias+resid, g3,b3)
// LNMODE 2: o = LN(acc+bias+resid, g3,b3) -> out1; out2 = LN(o, g1,b1)
// ---------------------------------------------------------------------------
template<int LNMODE, int NGRP>
__global__ void __launch_bounds__(256, 2)
gemm256e_kernel(const float* __restrict__ A,
                const float* __restrict__ W,
                const float* __restrict__ bias,
                const float* __restrict__ resid,
                const float* __restrict__ g3,
                const float* __restrict__ b3,
                const float* __restrict__ g1,
                const float* __restrict__ b1,
                float* __restrict__ out1,
                float* __restrict__ out2,
                int K, long sAg, long sWg)
{
    extern __shared__ uint32_t dyn[];
    constexpr int AW = 64 * 36;            // 2304
    constexpr int SW = AW + 32 * 264;      // 10752 words / stage
    constexpr int N = 256;

    int tid  = threadIdx.x;
    int warp = tid >> 5;
    int lane = tid & 31;
    int wm = (warp & 1) * 32;
    int wn = (warp >> 1) * 64;
    int gID = lane >> 2;
    int tig = lane & 3;
    int rowBase = blockIdx.y * 64;

    int nkpg = K >> 5;
    int nS = NGRP * nkpg;

    auto stage = [&](int buf, int s) {
        int g = s / nkpg;
        int k0 = (s % nkpg) << 5;
        const float* Ab = A + (long)g * sAg;
        const float* Wb = W + (long)g * sWg;
        uint32_t* As = dyn + buf * SW;
        uint32_t* Bs = dyn + buf * SW + AW;
#pragma unroll
        for (int it = 0; it < 2; it++) {           // A: 64x32 = 512 float4
            int f = tid + it * 256;
            int r = f >> 3, k4 = (f & 7) * 4;
            int m = rowBase + r;
            if (NGRP == 2 && g == 1) m = (m & ~511) + 511 - (m & 511);
            asm volatile("cp.async.ca.shared.global [%0], [%1], 16;\n"
                         :: "r"(smem_u32(&As[r * 36 + k4])),
                            "l"(Ab + (long)m * K + k0 + k4));
        }
#pragma unroll
        for (int it = 0; it < 8; it++) {           // B: 32x256 = 2048 float4
            int f = tid + it * 256;
            int kr = f >> 6, n4 = (f & 63) * 4;
            asm volatile("cp.async.ca.shared.global [%0], [%1], 16;\n"
                         :: "r"(smem_u32(&Bs[kr * 264 + n4])),
                            "l"(Wb + (long)(k0 + kr) * N + n4));
        }
        asm volatile("cp.async.commit_group;\n");
    };

    float acc[2][8][4];
#pragma unroll
    for (int a = 0; a < 2; a++)
#pragma unroll
        for (int b = 0; b < 8; b++)
#pragma unroll
            for (int c = 0; c < 4; c++) acc[a][b][c] = 0.f;

    auto compute = [&](int buf) {
        uint32_t* As = dyn + buf * SW;
        uint32_t* Bs = dyn + buf * SW + AW;
#pragma unroll
        for (int ks = 0; ks < 32; ks += 8) {
            uint32_t af[2][4];
#pragma unroll
            for (int mt = 0; mt < 2; mt++) {
                int row = wm + mt * 16 + gID;
                af[mt][0] = As[row * 36 + ks + tig] + 0x1000u;
                af[mt][1] = As[(row + 8) * 36 + ks + tig] + 0x1000u;
                af[mt][2] = As[row * 36 + ks + tig + 4] + 0x1000u;
                af[mt][3] = As[(row + 8) * 36 + ks + tig + 4] + 0x1000u;
            }
#pragma unroll
            for (int nt = 0; nt < 8; nt++) {
                int col = wn + nt * 8 + gID;
                uint32_t bf0 = Bs[(ks + tig) * 264 + col];
                uint32_t bf1 = Bs[(ks + tig + 4) * 264 + col];
#pragma unroll
                for (int mt = 0; mt < 2; mt++) {
                    asm volatile(
                        "mma.sync.aligned.m16n8k8.row.col.f32.tf32.tf32.f32 "
                        "{%0,%1,%2,%3}, {%4,%5,%6,%7}, {%8,%9}, {%0,%1,%2,%3};\n"
                        : "+f"(acc[mt][nt][0]), "+f"(acc[mt][nt][1]),
                          "+f"(acc[mt][nt][2]), "+f"(acc[mt][nt][3])
                        : "r"(af[mt][0]), "r"(af[mt][1]),
                          "r"(af[mt][2]), "r"(af[mt][3]),
                          "r"(bf0), "r"(bf1));
                }
            }
        }
    };

    // R6-proven 2-stage double-buffer (two barriers per slab, no race)
    stage(0, 0);
    for (int s = 0; s < nS; s++) {
        if (s + 1 < nS) {
            stage((s + 1) & 1, s + 1);
            asm volatile("cp.async.wait_group 1;\n");
        } else {
            asm volatile("cp.async.wait_group 0;\n");
        }
        __syncthreads();
        compute(s & 1);
        __syncthreads();
    }

    // epilogue: acc+bias -> smem scratch, then warp-per-token LN (8 rows/warp)
    float* scr = (float*)dyn;           // [64][260] = 66560 B (fits in dyn)
#pragma unroll
    for (int mt = 0; mt < 2; mt++) {
        int row0 = wm + mt * 16 + gID;
#pragma unroll
        for (int nt = 0; nt < 8; nt++) {
            int col = wn + nt * 8 + tig * 2;
            float b0 = bias[col], b1 = bias[col + 1];
            scr[row0 * 260 + col]           = acc[mt][nt][0] + b0;
            scr[row0 * 260 + col + 1]       = acc[mt][nt][1] + b1;
            scr[(row0 + 8) * 260 + col]     = acc[mt][nt][2] + b0;
            scr[(row0 + 8) * 260 + col + 1] = acc[mt][nt][3] + b1;
        }
    }
    __syncthreads();
#pragma unroll
    for (int rr = 0; rr < 8; rr++) {
        int r = warp * 8 + rr;
        long m = rowBase + r;
        float a[8], o[8];
        const float* rp = resid + m * 256 + lane * 8;
#pragma unroll
        for (int i = 0; i < 8; i++)
            a[i] = scr[r * 260 + lane * 8 + i] + rp[i];
        warp_ln8(a, g3, b3, lane, o);
        float4* o1 = (float4*)(out1 + m * 256 + lane * 8);
        o1[0] = make_float4(o[0], o[1], o[2], o[3]);
        o1[1] = make_float4(o[4], o[5], o[6], o[7]);
        if (LNMODE == 2 && out2) {
            float o2[8];
            warp_ln8(o, g1, b1, lane, o2);
            float4* p2 = (float4*)(out2 + m * 256 + lane * 8);
            p2[0] = make_float4(o2[0], o2[1], o2[2], o2[3]);
            p2[1] = make_float4(o2[4], o2[5], o2[6], o2[7]);
        }
    }
}

// ---------------------------------------------------------------------------
// depthwise causal conv (K=4) + bias + silu; 4 t-outputs per thread
// ---------------------------------------------------------------------------
__global__ void conv_silu_kernel(const float* __restrict__ xz,
                                 const float* __restrict__ convw,
                                 const float* __restrict__ convb,
                                 float* __restrict__ xc)
{
    long i = (long)blockIdx.x * 256 + threadIdx.x;
    if (i >= 2 * MTOK * 64) return;
    int d = (int)(i & 255);
    long q = i >> 8;
    int t0 = (int)(q & 127) * 4;
    int b  = (int)((q >> 7) & 15);
    int g  = (int)(q >> 11);

    const float4 w4 = *(const float4*)(convw + ((long)g * 256 + d) * 4);
    float bias = convb[(long)g * 256 + d];

    long mrow = (long)g * MTOK + (long)b * 512 + t0;
    const float* xp = xz + mrow * 512 + d;
    float xv[7];
#pragma unroll
    for (int j = 0; j < 7; j++) {
        int t = t0 - 3 + j;
        xv[j] = (t >= 0) ? xp[(long)(j - 3) * 512] : 0.f;
    }
    float* op = xc + mrow * 256 + d;
#pragma unroll
    for (int j = 0; j < 4; j++) {
        float acc = bias;
        acc = fmaf(xv[j],     w4.x, acc);
        acc = fmaf(xv[j + 1], w4.y, acc);
        acc = fmaf(xv[j + 2], w4.z, acc);
        acc = fmaf(xv[j + 3], w4.w, acc);
        op[(long)j * 256] = acc / (1.f + __expf(-acc));
    }
}

// ---------------------------------------------------------------------------
// Selective scan, 8 lanes per (g,b,d) group, 2 states per lane, pipelined.
// ---------------------------------------------------------------------------
__global__ void __launch_bounds__(256)
scan_kernel(const float* __restrict__ dt,
            const float* __restrict__ xc,
            const float* __restrict__ dbc,
            const float* __restrict__ xz,
            const float* __restrict__ alog,
            const float* __restrict__ dpar,
            float* __restrict__ y)
{
    int gidx = blockIdx.x * 32 + (threadIdx.x >> 3);
    int li = threadIdx.x & 7;
    int g = gidx >> 12;
    int b = (gidx >> 8) & 15;
    int d = gidx & 255;

    const float2 al = *(const float2*)&alog[((long)(g * 256 + d)) * 16 + li * 2];
    const float L2E = 1.4426950408889634f;
    float A0 = -__expf(al.x) * L2E;
    float A1 = -__expf(al.y) * L2E;
    float dp = dpar[(long)g * 256 + d];

    long mbase = (long)g * MTOK + (long)b * 512;
    const float* dtp = dt + mbase * 256 + d;
    const float* xcp = xc + mbase * 256 + d;
    const float* dbp = dbc + mbase * 40;
    const float* zp  = xz + mbase * 512 + 256 + d;
    float* yp = y + mbase * 256 + d;

    float h0 = 0.f, h1 = 0.f;

    float dtv_n = dtp[0];
    float xv_n  = xcp[0];
    float z_n   = zp[0];
    float2 B_n  = *(const float2*)&dbp[8 + li * 2];
    float2 C_n  = *(const float2*)&dbp[24 + li * 2];

    for (int t = 0; t < 512; t++) {
        float dtv = dtv_n, xv = xv_n, z = z_n;
        float2 Bv = B_n, Cv = C_n;
        long tn = (t + 1 < 512) ? t + 1 : 511;
        dtv_n = dtp[tn * 256];
        xv_n  = xcp[tn * 256];
        z_n   = zp[tn * 512];
        B_n   = *(const float2*)&dbp[tn * 40 + 8 + li * 2];
        C_n   = *(const float2*)&dbp[tn * 40 + 24 + li * 2];

        float dx = dtv * xv;
        h0 = exp2f(dtv * A0) * h0 + dx * Bv.x;
        h1 = exp2f(dtv * A1) * h1 + dx * Bv.y;
        float p = h0 * Cv.x + h1 * Cv.y;
        p += __shfl_xor_sync(0xffffffffu, p, 4);
        p += __shfl_xor_sync(0xffffffffu, p, 2);
        p += __shfl_xor_sync(0xffffffffu, p, 1);
        if (li == 0) {
            float sz = z / (1.f + __expf(-z));
            yp[(long)t * 256] = (p + dp * xv) * sz;
        }
    }
}

// ---------------------------------------------------------------------------
// Launch helpers
// ---------------------------------------------------------------------------
constexpr int SMEM128 = 3 * (128 * 36 + 32 * 136) * 4;
constexpr int SMEM64  = 3 * (64 * 36 + 32 * 136) * 4 + 2048;
constexpr int SMEM256E = 2 * (64 * 36 + 32 * 264) * 4;        // 86016 B

template<int ACT, bool AREV>
static void launch_tf128(const float* A, const float* W, const float* bias, float* C,
                         int M, int N, int K, int lda, int G,
                         long sAg, long sWg, long sCg, long sBg)
{
    cudaFuncSetAttribute(tf128_kernel<ACT, AREV>,
                         cudaFuncAttributeMaxDynamicSharedMemorySize, SMEM128);
    dim3 grid(N / 128, M / 128, G);
    tf128_kernel<ACT, AREV><<<grid, 256, SMEM128>>>(A, W, bias, C, M, N, K, lda,
                                                    sAg, sWg, sCg, sBg);
}

template<int ACT, bool NG, bool DTF>
static void launch_tf64(const float* A, const float* W, const float* bias, float* C,
                        int M, int N, int K, int G,
                        long sAg, long sWg, long sCg,
                        const float* dtw = nullptr, const float* dtb = nullptr,
                        float* DTout = nullptr)
{
    cudaFuncSetAttribute(tf64_kernel<ACT, NG, DTF>,
                         cudaFuncAttributeMaxDynamicSharedMemorySize, SMEM64);
    dim3 grid((N + 127) / 128, M / 64, G);
    tf64_kernel<ACT, NG, DTF><<<grid, 256, SMEM64>>>(
        A, W, bias, C, M, N, K, sAg, sWg, sCg, dtw, dtb, DTout);
}

template<int LNMODE, int NGRP>
static void launch_g256e(const float* A, const float* W, const float* bias,
                         const float* resid,
                         const float* g3, const float* b3,
                         const float* g1, const float* b1,
                         float* out1, float* out2,
                         int K, long sAg, long sWg)
{
    cudaFuncSetAttribute(gemm256e_kernel<LNMODE, NGRP>,
                         cudaFuncAttributeMaxDynamicSharedMemorySize, SMEM256E);
    dim3 grid(1, (int)(MTOK / 64), 1);
    gemm256e_kernel<LNMODE, NGRP><<<grid, 256, SMEM256E>>>(
        A, W, bias, resid, g3, b3, g1, b1, out1, out2, K, sAg, sWg);
}

extern "C" void kernel_launch(void* const* d_in, const int* in_sizes, int n_in,
                              void* d_out, int out_size)
{
    const float* input_ids = (const float*)d_in[0];
    const float* proj_w    = (const float*)d_in[1];
    const float* proj_b    = (const float*)d_in[2];
    const float* ln0_g     = (const float*)d_in[3];
    const float* ln0_b     = (const float*)d_in[4];
    const float* ln1_g     = (const float*)d_in[5];
    const float* ln1_b     = (const float*)d_in[6];
    const float* ip_w      = (const float*)d_in[7];
    const float* ip_b      = (const float*)d_in[8];
    const float* s_inw     = (const float*)d_in[9];
    const float* s_convw   = (const float*)d_in[10];
    const float* s_convb   = (const float*)d_in[11];
    const float* s_xw      = (const float*)d_in[12];
    const float* s_dtw     = (const float*)d_in[13];
    const float* s_dtb     = (const float*)d_in[14];
    const float* s_alog    = (const float*)d_in[15];
    const float* s_d       = (const float*)d_in[16];
    const float* s_outw    = (const float*)d_in[17];
    const float* op_w      = (const float*)d_in[18];
    const float* op_b      = (const float*)d_in[19];
    const float* ln2_g     = (const float*)d_in[20];
    const float* ln2_b     = (const float*)d_in[21];
    const float* f_w1      = (const float*)d_in[22];
    const float* f_b1      = (const float*)d_in[23];
    const float* f_w2      = (const float*)d_in[24];
    const float* f_b2      = (const float*)d_in[25];
    const float* ln3_g     = (const float*)d_in[26];
    const float* ln3_b     = (const float*)d_in[27];

    float* base = nullptr;
    cudaGetSymbolAddress((void**)&base, g_buf);

    float* X    = base + OFF_X;
    float* LNb  = base + OFF_LN;
    float* XZ   = base + OFF_XZ;
    float* XC   = base + OFF_XC;
    float* DBC  = base + OFF_DBC;
    float* DT   = base + OFF_DT;
    float* Y    = base + OFF_Y;
    float* FF   = base + OFF_FF;
    float* W2C  = base + OFF_W2C;
    float* WXZ  = base + OFF_WXZ;
    float* BXZ  = base + OFF_BXZ;

    const int M = (int)MTOK;
    const int CONV_BLOCKS = (int)(2 * MTOK * 64 / 256);
    const int LN_BLOCKS = (int)(MTOK / 8);

    // --- precompute composed weights -------------------------------------
    launch_tf64<0, false, false>(s_outw, op_w, nullptr, W2C,
                                 256, 256, 128, 24, 32768, 32768, 65536);
    for (int g = 0; g < 2; g++) {
        launch_tf128<0, false>(ip_w + g * 128, s_inw + (long)g * 65536, nullptr,
                               WXZ + (long)g * 131072,
                               256, 512, 128, 256, 12,
                               65536, 131072, 262144, 0);
    }
    bxz_kernel<<<48, 256>>>(ip_b, s_inw, BXZ);

    // --- embedding + first LN1 -------------------------------------------
    embed_ln_kernel<<<M, 256>>>(input_ids, proj_w, proj_b, ln0_g, ln0_b, X);
    ln_kernel<<<LN_BLOCKS, 256>>>(X, ln1_g, ln1_b, LNb);

    for (int l = 0; l < 12; l++) {
        // xz = LN1[rev_g] @ WXZ[l][g] + BXZ[l][g]
        launch_tf128<0, true>(LNb, WXZ + (long)l * 262144, BXZ + (long)l * 1024, XZ,
                              M, 512, 256, 256, 2,
                              0, 131072, MTOK * 512, 512);
        // conv + silu
        conv_silu_kernel<<<CONV_BLOCKS, 256>>>(XZ, s_convw + (long)l * 2 * 256 * 4,
                                               s_convb + (long)l * 2 * 256, XC);
        // dbc = xc @ xw (N=40 guarded) + fused dt
        launch_tf64<0, true, true>(XC, s_xw + (long)l * 2 * 256 * 40, nullptr, DBC,
                                   M, 40, 256, 2, MTOK * 256, 256 * 40, MTOK * 40,
                                   s_dtw + (long)l * 2 * 8 * 256,
                                   s_dtb + (long)l * 2 * 256, DT);
        // selective scan + fused silu(z) gate
        scan_kernel<<<256, 256>>>(DT, XC, DBC, XZ,
                                  s_alog + (long)l * 2 * 256 * 16,
                                  s_d + (long)l * 2 * 256, Y);
        // fused outw∘opw + op_b + residual + LN2 -> X
        launch_g256e<1, 2>(Y, W2C + (long)l * 2 * 65536, op_b + l * 256,
                           X, ln2_g + l * 256, ln2_b + l * 256,
                           nullptr, nullptr, X, nullptr,
                           256, MTOK * 256, 65536);
        // ff = gelu(x @ w1 + b1)
        launch_tf128<2, false>(X, f_w1 + (long)l * 256 * 1024, f_b1 + l * 1024, FF,
                               M, 1024, 256, 256, 1, 0, 0, 0, 0);
        // f = ff @ w2 + b2 + residual X + LN3 -> dst ; LN1(next) -> LNb
        float* dst = (l == 11) ? (float*)d_out : X;
        float* lnb = (l == 11) ? nullptr : LNb;
        const float* g1 = ln1_g + (l + 1 < 12 ? (l + 1) * 256 : 0);
        const float* b1 = ln1_b + (l + 1 < 12 ? (l + 1) * 256 : 0);
        launch_g256e<2, 1>(FF, f_w2 + (long)l * 1024 * 256, f_b2 + l * 256,
                           X, ln3_g + l * 256, ln3_b + l * 256,
                           g1, b1, dst, lnb,
                           1024, 0, 0);
    }
}